// round 12
// baseline (speedup 1.0000x reference)
#include <cuda_runtime.h>
#include <cuda_fp16.h>
#include <cstdint>

#define T_TOK 2048
#define HDIM  1024
#define FFDIM 4096
#define NEXP  64
#define TOPK  8
#define MDIM  512
#define NASSIGN (T_TOK * TOPK)

// fp16 tile gemm geometry
#define BM 128
#define BN 128
#define BK 32
#define ASTR_B 80     // bytes per A smem row (32 fp16 + 8 pad)
#define BSTR_B 272    // bytes per B smem row (128 fp16 + 8 pad)
#define ASZ_B (BM * ASTR_B)          // 10240
#define BSZ_B (BK * BSTR_B)          // 8704
#define STAGE_B (ASZ_B + BSZ_B)      // 18944
#define NSTG 3
#define SMEM3 (NSTG * STAGE_B)       // 56832 bytes (dynamic)

// ---------------- scratch (static device globals; no allocation) -------------
__device__ __half g_xh [(size_t)T_TOK * HDIM];
__device__ __half g_s1h[(size_t)HDIM * FFDIM];
__device__ __half g_s2h[(size_t)FFDIM * HDIM];
__device__ __half g_w1h[(size_t)NEXP * HDIM * MDIM];
__device__ __half g_w2h[(size_t)NEXP * MDIM * HDIM];
__device__ __half g_h1h[(size_t)T_TOK * FFDIM];
__device__ __half g_acth[(size_t)NASSIGN * MDIM];
__device__ float g_eout[(size_t)NASSIGN * HDIM];   // per-assignment expert output
__device__ int   g_perm_tok[NASSIGN];
__device__ float g_perm_w[NASSIGN];
__device__ int   g_topk_idx[NASSIGN];
__device__ float g_topk_w[NASSIGN];
__device__ int   g_pos[NASSIGN];                   // token-order -> permuted slot
__device__ int   g_counts[NEXP];
__device__ int   g_offs[NEXP + 1];

__device__ __forceinline__ float silu_f(float v) {
    return v / (1.0f + __expf(-v));
}

__device__ __forceinline__ void cp16(unsigned sdst, const void* gsrc, int bytes) {
    asm volatile("cp.async.cg.shared.global [%0], [%1], 16, %2;\n"
                 :: "r"(sdst), "l"(gsrc), "r"(bytes));
}
__device__ __forceinline__ void cp_commit() {
    asm volatile("cp.async.commit_group;\n" ::);
}

__device__ __forceinline__ void ldsm4(unsigned& r0, unsigned& r1, unsigned& r2, unsigned& r3, unsigned addr) {
    asm volatile("ldmatrix.sync.aligned.m8n8.x4.shared.b16 {%0,%1,%2,%3}, [%4];\n"
                 : "=r"(r0), "=r"(r1), "=r"(r2), "=r"(r3) : "r"(addr));
}
__device__ __forceinline__ void ldsm4t(unsigned& r0, unsigned& r1, unsigned& r2, unsigned& r3, unsigned addr) {
    asm volatile("ldmatrix.sync.aligned.m8n8.x4.trans.shared.b16 {%0,%1,%2,%3}, [%4];\n"
                 : "=r"(r0), "=r"(r1), "=r"(r2), "=r"(r3) : "r"(addr));
}
__device__ __forceinline__ void mma16816(float d[4], const unsigned a[4], const unsigned b[2]) {
    asm volatile(
        "mma.sync.aligned.m16n8k16.row.col.f32.f16.f16.f32 "
        "{%0,%1,%2,%3}, {%4,%5,%6,%7}, {%8,%9}, {%0,%1,%2,%3};\n"
        : "+f"(d[0]), "+f"(d[1]), "+f"(d[2]), "+f"(d[3])
        : "r"(a[0]), "r"(a[1]), "r"(a[2]), "r"(a[3]),
          "r"(b[0]), "r"(b[1]));
}

// ---------------- fp32 -> fp16 conversion (16B stores, small grid) -----------
__global__ void f2h_kernel(const float4* __restrict__ src, uint4* __restrict__ dst, long n8) {
    long stride = (long)gridDim.x * blockDim.x;
    for (long i = (long)blockIdx.x * blockDim.x + threadIdx.x; i < n8; i += stride) {
        float4 a = src[2 * i], b = src[2 * i + 1];
        uint4 o;
        __half2* h = (__half2*)&o;
        h[0] = __floats2half2_rn(a.x, a.y);
        h[1] = __floats2half2_rn(a.z, a.w);
        h[2] = __floats2half2_rn(b.x, b.y);
        h[3] = __floats2half2_rn(b.z, b.w);
        dst[i] = o;
    }
}

// ---------------- tiny bookkeeping kernels ----------------------------------
__global__ void zero_small_kernel() {
    int i = threadIdx.x;
    if (i < NEXP) g_counts[i] = 0;
}

// fused exclusive scan + scatter (single block, smem offsets/fills)
__global__ void __launch_bounds__(1024) scan_scatter_kernel() {
    __shared__ int soffs[NEXP];
    __shared__ int sfill[NEXP];
    const int tid = threadIdx.x;
    if (tid == 0) {
        int s = 0;
        for (int e = 0; e < NEXP; e++) { soffs[e] = s; g_offs[e] = s; s += g_counts[e]; }
        g_offs[NEXP] = s;
    }
    if (tid < NEXP) sfill[tid] = 0;
    __syncthreads();
    for (int idx = tid; idx < NASSIGN; idx += 1024) {
        int e = g_topk_idx[idx];
        int pos = soffs[e] + atomicAdd(&sfill[e], 1);
        g_perm_tok[pos] = idx / TOPK;
        g_perm_w[pos]   = g_topk_w[idx];
        g_pos[idx]      = pos;
    }
}

// ---------------- router top-8 + softmax (one warp per token) ---------------
__global__ void topk_kernel(const float* __restrict__ logits) {
    int warp = threadIdx.x >> 5;
    int lane = threadIdx.x & 31;
    int t = blockIdx.x * (blockDim.x >> 5) + warp;
    if (t >= T_TOK) return;

    float v0 = logits[t * NEXP + lane];
    float v1 = logits[t * NEXP + 32 + lane];

    float vals[TOPK];
    int   ids[TOPK];
    #pragma unroll
    for (int r = 0; r < TOPK; r++) {
        float m;  int mi;
        if (v0 >= v1) { m = v0; mi = lane; } else { m = v1; mi = lane + 32; }
        #pragma unroll
        for (int off = 16; off > 0; off >>= 1) {
            float om = __shfl_xor_sync(0xFFFFFFFFu, m, off);
            int   oi = __shfl_xor_sync(0xFFFFFFFFu, mi, off);
            if (om > m || (om == m && oi < mi)) { m = om; mi = oi; }
        }
        vals[r] = m; ids[r] = mi;
        if (mi == lane)            v0 = -1e30f;
        else if (mi == lane + 32)  v1 = -1e30f;
    }

    float s = 0.0f;
    #pragma unroll
    for (int r = 0; r < TOPK; r++) s += expf(vals[r] - vals[0]);

    if (lane < TOPK) {
        float myv = 0.0f; int myi = 0;
        #pragma unroll
        for (int r = 0; r < TOPK; r++)
            if (lane == r) { myv = vals[r]; myi = ids[r]; }
        float w = expf(myv - vals[0]) / s;
        g_topk_idx[t * TOPK + lane] = myi;
        g_topk_w[t * TOPK + lane]   = w;
        atomicAdd(&g_counts[myi], 1);
    }
}

// ---------------- final combine: out[t] += sum_k w_k * eout[pos_k] ----------
__global__ void __launch_bounds__(256)
combine_kernel(float* __restrict__ out, const float* __restrict__ eout) {
    const int t = blockIdx.x;
    __shared__ float w[TOPK];
    __shared__ int   ps[TOPK];
    if (threadIdx.x < TOPK) {
        w[threadIdx.x]  = g_topk_w[t * TOPK + threadIdx.x];
        ps[threadIdx.x] = g_pos[t * TOPK + threadIdx.x];
    }
    __syncthreads();
    const int h = threadIdx.x * 4;
    float4 acc = *(const float4*)&out[(long)t * HDIM + h];
    #pragma unroll
    for (int k = 0; k < TOPK; k++) {
        const float4 v = *(const float4*)&eout[(long)ps[k] * HDIM + h];
        acc.x += w[k] * v.x;
        acc.y += w[k] * v.y;
        acc.z += w[k] * v.z;
        acc.w += w[k] * v.w;
    }
    *(float4*)&out[(long)t * HDIM + h] = acc;
}

// ---------------- exact fp32 64x64 GEMM (router only) -----------------------
__global__ void __launch_bounds__(256)
gemm64(const float* __restrict__ A, const float* __restrict__ B,
       float* __restrict__ C, int M, int Kd, int lda, int ldb, int ldc)
{
    __shared__ float As[16 * 65];
    __shared__ float Bs[16 * 64];
    const int tid = threadIdx.x;
    const int row0 = blockIdx.y * 64;
    const int col0 = blockIdx.x * 64;

    const int am = tid >> 2;
    const int ak = (tid & 3) << 2;
    const int bn = (tid & 15) << 2;
    const int bk = tid >> 4;
    const int ty = tid >> 4, tx = tid & 15;

    float acc[4][4];
    #pragma unroll
    for (int i = 0; i < 4; i++)
        #pragma unroll
        for (int j = 0; j < 4; j++) acc[i][j] = 0.0f;

    for (int k0 = 0; k0 < Kd; k0 += 16) {
        float4 av = *(const float4*)(A + (long)(row0 + am) * lda + k0 + ak);
        As[(ak + 0) * 65 + am] = av.x;
        As[(ak + 1) * 65 + am] = av.y;
        As[(ak + 2) * 65 + am] = av.z;
        As[(ak + 3) * 65 + am] = av.w;
        float4 bv = *(const float4*)(B + (long)(k0 + bk) * ldb + col0 + bn);
        *(float4*)&Bs[bk * 64 + bn] = bv;
        __syncthreads();
        #pragma unroll
        for (int k = 0; k < 16; k++) {
            float a0 = As[k * 65 + ty * 4 + 0];
            float a1 = As[k * 65 + ty * 4 + 1];
            float a2 = As[k * 65 + ty * 4 + 2];
            float a3 = As[k * 65 + ty * 4 + 3];
            float b0 = Bs[k * 64 + tx * 4 + 0];
            float b1 = Bs[k * 64 + tx * 4 + 1];
            float b2 = Bs[k * 64 + tx * 4 + 2];
            float b3 = Bs[k * 64 + tx * 4 + 3];
            acc[0][0] += a0 * b0; acc[0][1] += a0 * b1; acc[0][2] += a0 * b2; acc[0][3] += a0 * b3;
            acc[1][0] += a1 * b0; acc[1][1] += a1 * b1; acc[1][2] += a1 * b2; acc[1][3] += a1 * b3;
            acc[2][0] += a2 * b0; acc[2][1] += a2 * b1; acc[2][2] += a2 * b2; acc[2][3] += a2 * b3;
            acc[3][0] += a3 * b0; acc[3][1] += a3 * b1; acc[3][2] += a3 * b2; acc[3][3] += a3 * b3;
        }
        __syncthreads();
    }
    const int col = col0 + tx * 4;
    #pragma unroll
    for (int i = 0; i < 4; i++) {
        float* cp = C + (long)(row0 + ty * 4 + i) * ldc + col;
        #pragma unroll
        for (int j = 0; j < 4; j++) cp[j] = acc[i][j];
    }
}

// ---------------- fp16 tensor-core tile GEMM 128x128x32, 3-stage -------------
// EXPERT: blockIdx.z selects expert window in g_offs + B stride
// GATHER: A row index = g_perm_tok[base + r]
// EPI: 0 = fp32 store (at base+grow when EXPERT), 1 = silu -> fp16 store
template<bool EXPERT, bool GATHER, int EPI>
__global__ void __launch_bounds__(256)
gemm_h(const __half* __restrict__ A, const __half* __restrict__ B,
       void* __restrict__ Cv, int Kd, int lda, int ldb, int ldc, long strideB)
{
    extern __shared__ char sm[];
    const int tid  = threadIdx.x;
    const int wid  = tid >> 5, lane = tid & 31;
    const int wM   = wid & 1,  wN   = wid >> 1;      // 2 x 4 warps, warp tile 64x32
    const int l16  = lane & 15, lh = lane >> 4;

    int base = 0, nrows = T_TOK;
    const __half* Bp = B;
    if (EXPERT) {
        int e = blockIdx.z;
        base  = g_offs[e];
        nrows = g_offs[e + 1] - base;
        Bp    = B + (long)e * strideB;
    }
    const int row0 = blockIdx.y * BM;
    if (EXPERT && row0 >= nrows) return;
    const int col0 = blockIdx.x * BN;

    const unsigned smu = (unsigned)__cvta_generic_to_shared(sm);
    const unsigned As_u = smu;              // stage0 A
    const unsigned Bs_u = smu + ASZ_B;      // stage0 B

    // cp.async bookkeeping: 2 A-chunks + 2 B-chunks per thread per stage
    const __half* asrc[2]; unsigned adst[2]; int abytes[2];
    #pragma unroll
    for (int i = 0; i < 2; i++) {
        int idx = tid + i * 256;
        int r = idx >> 2, q = idx & 3;              // 4 x 16B chunks per 32-fp16 row
        adst[i] = As_u + (unsigned)(r * ASTR_B + q * 16);
        int gr = row0 + r;
        long ar = -1;
        if (gr < nrows)
            ar = GATHER ? (long)g_perm_tok[base + gr]
                        : (EXPERT ? (long)(base + gr) : (long)gr);
        abytes[i] = (ar >= 0) ? 16 : 0;
        asrc[i] = A + (ar >= 0 ? ar : 0) * (long)lda + q * 8;
    }
    const __half* bsrc[2]; unsigned bdst[2];
    #pragma unroll
    for (int i = 0; i < 2; i++) {
        int idx = tid + i * 256;
        int br = idx >> 4, q = idx & 15;            // 16 x 16B chunks per 128-fp16 row
        bdst[i] = Bs_u + (unsigned)(br * BSTR_B + q * 16);
        bsrc[i] = Bp + (long)br * ldb + col0 + q * 8;
    }

    float acc[4][4][4];
    #pragma unroll
    for (int mi = 0; mi < 4; mi++)
        #pragma unroll
        for (int ni = 0; ni < 4; ni++)
            #pragma unroll
            for (int j = 0; j < 4; j++) acc[mi][ni][j] = 0.0f;

    const int nk = Kd / BK;

    // prologue: prefetch chunks 0..NSTG-2
    #pragma unroll
    for (int c = 0; c < NSTG - 1; c++) {
        const unsigned soff = (unsigned)(c * STAGE_B);
        const int k0 = c * BK;
        #pragma unroll
        for (int i = 0; i < 2; i++) cp16(adst[i] + soff, asrc[i] + k0, abytes[i]);
        #pragma unroll
        for (int i = 0; i < 2; i++) cp16(bdst[i] + soff, bsrc[i] + (long)k0 * ldb, 16);
        cp_commit();
    }

    // ldmatrix base addresses (stage-relative)
    const unsigned a_base = As_u + (unsigned)((wM * 64 + l16) * ASTR_B + lh * 16);
    const unsigned b_base = Bs_u + (unsigned)(l16 * BSTR_B + (wN * 32) * 2 + lh * 16);

    int rd_st = 0, wr_st = NSTG - 1;
    for (int it = 0; it < nk; it++) {
        asm volatile("cp.async.wait_group %0;\n" :: "n"(NSTG - 2));
        __syncthreads();

        // prefetch chunk it+NSTG-1 into stage wr_st (read stage of iter it-1;
        // the sync above guarantees all warps are done with it)
        {
            const int nc = it + NSTG - 1;
            if (nc < nk) {
                const unsigned soff = (unsigned)(wr_st * STAGE_B);
                const int k0 = nc * BK;
                #pragma unroll
                for (int i = 0; i < 2; i++) cp16(adst[i] + soff, asrc[i] + k0, abytes[i]);
                #pragma unroll
                for (int i = 0; i < 2; i++) cp16(bdst[i] + soff, bsrc[i] + (long)k0 * ldb, 16);
            }
            cp_commit();   // uniform group accounting
        }

        const unsigned stoff = (unsigned)(rd_st * STAGE_B);
        #pragma unroll
        for (int ks = 0; ks < 2; ks++) {
            unsigned a[4][4], b[4][2];
            #pragma unroll
            for (int mi = 0; mi < 4; mi++)
                ldsm4(a[mi][0], a[mi][1], a[mi][2], a[mi][3],
                      a_base + stoff + (unsigned)(mi * 16 * ASTR_B + ks * 32));
            #pragma unroll
            for (int nb = 0; nb < 2; nb++)
                ldsm4t(b[nb * 2][0], b[nb * 2][1], b[nb * 2 + 1][0], b[nb * 2 + 1][1],
                       b_base + stoff + (unsigned)(ks * 16 * BSTR_B + nb * 32));
            #pragma unroll
            for (int mi = 0; mi < 4; mi++)
                #pragma unroll
                for (int ni = 0; ni < 4; ni++)
                    mma16816(acc[mi][ni], a[mi], b[ni]);
        }

        rd_st = (rd_st + 1 == NSTG) ? 0 : rd_st + 1;
        wr_st = (wr_st + 1 == NSTG) ? 0 : wr_st + 1;
    }

    // epilogue
    const int lq = lane >> 2, lr2 = (lane & 3) * 2;
    #pragma unroll
    for (int mi = 0; mi < 4; mi++) {
        #pragma unroll
        for (int s = 0; s < 2; s++) {
            const int grow = row0 + wM * 64 + mi * 16 + lq + s * 8;
            if (grow >= nrows) continue;
            if (EPI == 1) {
                const long cr = EXPERT ? (long)(base + grow) : (long)grow;
                __half* cp = (__half*)Cv + cr * ldc;
                #pragma unroll
                for (int ni = 0; ni < 4; ni++) {
                    const int col = col0 + wN * 32 + ni * 8 + lr2;
                    *(__half2*)&cp[col] = __floats2half2_rn(
                        silu_f(acc[mi][ni][2 * s]), silu_f(acc[mi][ni][2 * s + 1]));
                }
            } else {
                const long cr = EXPERT ? (long)(base + grow) : (long)grow;
                float* cp = (float*)Cv + cr * ldc;
                #pragma unroll
                for (int ni = 0; ni < 4; ni++) {
                    const int col = col0 + wN * 32 + ni * 8 + lr2;
                    *(float2*)&cp[col] = make_float2(acc[mi][ni][2 * s], acc[mi][ni][2 * s + 1]);
                }
            }
        }
    }
}

// ---------------- launch (multi-stream fork/join under graph capture) --------
extern "C" void kernel_launch(void* const* d_in, const int* in_sizes, int n_in,
                              void* d_out, int out_size)
{
    const float* x   = (const float*)d_in[0];   // [T, H]
    const float* Ws1 = (const float*)d_in[1];   // [H, FF]
    const float* Ws2 = (const float*)d_in[2];   // [FF, H]
    const float* Wg  = (const float*)d_in[3];   // [H, E]
    const float* W1  = (const float*)d_in[4];   // [E, H, M]
    const float* W2  = (const float*)d_in[5];   // [E, M, H]

    float* out    = (float*)d_out;                      // [T, H]
    float* logits = out + (size_t)T_TOK * HDIM;         // [T, E]

    __half *xh, *s1h, *s2h, *w1h, *w2h, *h1h, *acth;
    float* eout;
    cudaGetSymbolAddress((void**)&xh,  g_xh);
    cudaGetSymbolAddress((void**)&s1h, g_s1h);
    cudaGetSymbolAddress((void**)&s2h, g_s2h);
    cudaGetSymbolAddress((void**)&w1h, g_w1h);
    cudaGetSymbolAddress((void**)&w2h, g_w2h);
    cudaGetSymbolAddress((void**)&h1h, g_h1h);
    cudaGetSymbolAddress((void**)&acth, g_acth);
    cudaGetSymbolAddress((void**)&eout, g_eout);

    cudaFuncSetAttribute(gemm_h<false, false, 1>, cudaFuncAttributeMaxDynamicSharedMemorySize, SMEM3);
    cudaFuncSetAttribute(gemm_h<false, false, 0>, cudaFuncAttributeMaxDynamicSharedMemorySize, SMEM3);
    cudaFuncSetAttribute(gemm_h<true,  true,  1>, cudaFuncAttributeMaxDynamicSharedMemorySize, SMEM3);
    cudaFuncSetAttribute(gemm_h<true,  false, 0>, cudaFuncAttributeMaxDynamicSharedMemorySize, SMEM3);

    cudaStream_t sConv, sRoute, sExp;
    cudaStreamCreateWithFlags(&sConv,  cudaStreamNonBlocking);
    cudaStreamCreateWithFlags(&sRoute, cudaStreamNonBlocking);
    cudaStreamCreateWithFlags(&sExp,   cudaStreamNonBlocking);
    cudaEvent_t e0, eX, eWs1, eWs2, eW1, eW2, eRoute, eExp;
    cudaEventCreateWithFlags(&e0,     cudaEventDisableTiming);
    cudaEventCreateWithFlags(&eX,     cudaEventDisableTiming);
    cudaEventCreateWithFlags(&eWs1,   cudaEventDisableTiming);
    cudaEventCreateWithFlags(&eWs2,   cudaEventDisableTiming);
    cudaEventCreateWithFlags(&eW1,    cudaEventDisableTiming);
    cudaEventCreateWithFlags(&eW2,    cudaEventDisableTiming);
    cudaEventCreateWithFlags(&eRoute, cudaEventDisableTiming);
    cudaEventCreateWithFlags(&eExp,   cudaEventDisableTiming);

    // fork from capture stream
    cudaEventRecord(e0, 0);
    cudaStreamWaitEvent(sConv,  e0, 0);
    cudaStreamWaitEvent(sRoute, e0, 0);
    cudaStreamWaitEvent(sExp,   e0, 0);

    // -- conversion branch (small grids: DRAM-bound, minimal SM footprint) --
    f2h_kernel<<<512, 256, 0, sConv>>>((const float4*)Ws1, (uint4*)s1h, (long)HDIM * FFDIM / 8);
    cudaEventRecord(eWs1, sConv);
    f2h_kernel<<<512, 256, 0, sConv>>>((const float4*)Ws2, (uint4*)s2h, (long)FFDIM * HDIM / 8);
    cudaEventRecord(eWs2, sConv);
    f2h_kernel<<<512, 256, 0, sConv>>>((const float4*)W1, (uint4*)w1h, (long)NEXP * HDIM * MDIM / 8);
    cudaEventRecord(eW1, sConv);
    f2h_kernel<<<512, 256, 0, sConv>>>((const float4*)W2, (uint4*)w2h, (long)NEXP * MDIM * HDIM / 8);
    cudaEventRecord(eW2, sConv);

    // -- router branch --
    zero_small_kernel<<<1, 128, 0, sRoute>>>();
    gemm64<<<dim3(1, T_TOK / 64, 1), 256, 0, sRoute>>>(x, Wg, logits, T_TOK, HDIM, HDIM, NEXP, NEXP);
    topk_kernel<<<T_TOK / 8, 256, 0, sRoute>>>(logits);
    scan_scatter_kernel<<<1, 1024, 0, sRoute>>>();
    cudaEventRecord(eRoute, sRoute);

    // -- main (capture) stream: x conversion, then shared-expert chain --
    f2h_kernel<<<512, 256>>>((const float4*)x, (uint4*)xh, (long)T_TOK * HDIM / 8);
    cudaEventRecord(eX, 0);

    cudaStreamWaitEvent(0, eWs1, 0);
    gemm_h<false, false, 1><<<dim3(FFDIM / BN, T_TOK / BM, 1), 256, SMEM3>>>(
        xh, s1h, h1h, HDIM, HDIM, FFDIM, FFDIM, 0);

    cudaStreamWaitEvent(0, eWs2, 0);
    gemm_h<false, false, 0><<<dim3(HDIM / BN, T_TOK / BM, 1), 256, SMEM3>>>(
        h1h, s2h, out, FFDIM, FFDIM, HDIM, HDIM, 0);

    // -- expert branch (independent of shared chain) --
    cudaStreamWaitEvent(sExp, eX, 0);
    cudaStreamWaitEvent(sExp, eW1, 0);
    cudaStreamWaitEvent(sExp, eRoute, 0);
    gemm_h<true, true, 1><<<dim3(MDIM / BN, T_TOK / BM, NEXP), 256, SMEM3, sExp>>>(
        xh, w1h, acth, HDIM, HDIM, MDIM, MDIM, (long)HDIM * MDIM);
    cudaStreamWaitEvent(sExp, eW2, 0);
    gemm_h<true, false, 0><<<dim3(HDIM / BN, T_TOK / BM, NEXP), 256, SMEM3, sExp>>>(
        acth, w2h, eout, MDIM, MDIM, HDIM, HDIM, (long)MDIM * HDIM);
    cudaEventRecord(eExp, sExp);

    // -- join: combine expert contributions into out --
    cudaStreamWaitEvent(0, eExp, 0);
    combine_kernel<<<T_TOK, 256>>>(out, eout);

    cudaEventDestroy(e0);
    cudaEventDestroy(eX);
    cudaEventDestroy(eWs1);
    cudaEventDestroy(eWs2);
    cudaEventDestroy(eW1);
    cudaEventDestroy(eW2);
    cudaEventDestroy(eRoute);
    cudaEventDestroy(eExp);
    cudaStreamDestroy(sConv);
    cudaStreamDestroy(sRoute);
    cudaStreamDestroy(sExp);
}

// round 13
// speedup vs baseline: 1.5702x; 1.5702x over previous
#include <cuda_runtime.h>
#include <cuda_fp16.h>
#include <cstdint>

#define T_TOK 2048
#define HDIM  1024
#define FFDIM 4096
#define NEXP  64
#define TOPK  8
#define MDIM  512
#define NASSIGN (T_TOK * TOPK)

// fp16 tile gemm geometry
#define BM 128
#define BN 128
#define BK 32
#define ASTR_B 80     // bytes per A smem row (32 fp16 + 8 pad)
#define BSTR_B 272    // bytes per B smem row (128 fp16 + 8 pad)
#define ASZ_B (BM * ASTR_B)          // 10240
#define BSZ_B (BK * BSTR_B)          // 8704
#define STAGE_B (ASZ_B + BSZ_B)      // 18944
#define SMEM_B (2 * STAGE_B)         // 37888 (< 48KB static)

// ---------------- scratch (static device globals; no allocation) -------------
__device__ __half g_xh [(size_t)T_TOK * HDIM];
__device__ __half g_s1h[(size_t)HDIM * FFDIM];
__device__ __half g_s2h[(size_t)FFDIM * HDIM];
__device__ __half g_w1h[(size_t)NEXP * HDIM * MDIM];
__device__ __half g_w2h[(size_t)NEXP * MDIM * HDIM];
__device__ __half g_h1h[(size_t)T_TOK * FFDIM];
__device__ __half g_acth[(size_t)NASSIGN * MDIM];
__device__ int   g_perm_tok[NASSIGN];
__device__ float g_perm_w[NASSIGN];
__device__ int   g_topk_idx[NASSIGN];
__device__ float g_topk_w[NASSIGN];
__device__ int   g_counts[NEXP];
__device__ int   g_fill[NEXP];
__device__ int   g_offs[NEXP + 1];

__device__ __forceinline__ float silu_f(float v) {
    return v / (1.0f + __expf(-v));
}

__device__ __forceinline__ void cp16(unsigned sdst, const void* gsrc, int bytes) {
    asm volatile("cp.async.cg.shared.global [%0], [%1], 16, %2;\n"
                 :: "r"(sdst), "l"(gsrc), "r"(bytes));
}
__device__ __forceinline__ void cp_commit() {
    asm volatile("cp.async.commit_group;\n" ::);
}

__device__ __forceinline__ void ldsm4(unsigned& r0, unsigned& r1, unsigned& r2, unsigned& r3, unsigned addr) {
    asm volatile("ldmatrix.sync.aligned.m8n8.x4.shared.b16 {%0,%1,%2,%3}, [%4];\n"
                 : "=r"(r0), "=r"(r1), "=r"(r2), "=r"(r3) : "r"(addr));
}
__device__ __forceinline__ void ldsm4t(unsigned& r0, unsigned& r1, unsigned& r2, unsigned& r3, unsigned addr) {
    asm volatile("ldmatrix.sync.aligned.m8n8.x4.trans.shared.b16 {%0,%1,%2,%3}, [%4];\n"
                 : "=r"(r0), "=r"(r1), "=r"(r2), "=r"(r3) : "r"(addr));
}
__device__ __forceinline__ void mma16816(float d[4], const unsigned a[4], const unsigned b[2]) {
    asm volatile(
        "mma.sync.aligned.m16n8k16.row.col.f32.f16.f16.f32 "
        "{%0,%1,%2,%3}, {%4,%5,%6,%7}, {%8,%9}, {%0,%1,%2,%3};\n"
        : "+f"(d[0]), "+f"(d[1]), "+f"(d[2]), "+f"(d[3])
        : "r"(a[0]), "r"(a[1]), "r"(a[2]), "r"(a[3]),
          "r"(b[0]), "r"(b[1]));
}

// ---------------- fp32 -> fp16 conversion (16B stores, small grid) -----------
__global__ void f2h_kernel(const float4* __restrict__ src, uint4* __restrict__ dst, long n8) {
    long stride = (long)gridDim.x * blockDim.x;
    for (long i = (long)blockIdx.x * blockDim.x + threadIdx.x; i < n8; i += stride) {
        float4 a = src[2 * i], b = src[2 * i + 1];
        uint4 o;
        __half2* h = (__half2*)&o;
        h[0] = __floats2half2_rn(a.x, a.y);
        h[1] = __floats2half2_rn(a.z, a.w);
        h[2] = __floats2half2_rn(b.x, b.y);
        h[3] = __floats2half2_rn(b.z, b.w);
        dst[i] = o;
    }
}

// ---------------- tiny bookkeeping kernels ----------------------------------
__global__ void zero_small_kernel() {
    int i = threadIdx.x;
    if (i < NEXP) { g_counts[i] = 0; g_fill[i] = 0; }
}

__global__ void scan_kernel() {
    if (threadIdx.x == 0) {
        int s = 0;
        for (int e = 0; e < NEXP; e++) { g_offs[e] = s; s += g_counts[e]; }
        g_offs[NEXP] = s;
    }
}

__global__ void scatter_kernel() {
    int idx = blockIdx.x * blockDim.x + threadIdx.x;
    if (idx >= NASSIGN) return;
    int e = g_topk_idx[idx];
    int pos = g_offs[e] + atomicAdd(&g_fill[e], 1);
    g_perm_tok[pos] = idx / TOPK;
    g_perm_w[pos]   = g_topk_w[idx];
}

// ---------------- router top-8 + softmax (one warp per token) ---------------
__global__ void topk_kernel(const float* __restrict__ logits) {
    int warp = threadIdx.x >> 5;
    int lane = threadIdx.x & 31;
    int t = blockIdx.x * (blockDim.x >> 5) + warp;
    if (t >= T_TOK) return;

    float v0 = logits[t * NEXP + lane];
    float v1 = logits[t * NEXP + 32 + lane];

    float vals[TOPK];
    int   ids[TOPK];
    #pragma unroll
    for (int r = 0; r < TOPK; r++) {
        float m;  int mi;
        if (v0 >= v1) { m = v0; mi = lane; } else { m = v1; mi = lane + 32; }
        #pragma unroll
        for (int off = 16; off > 0; off >>= 1) {
            float om = __shfl_xor_sync(0xFFFFFFFFu, m, off);
            int   oi = __shfl_xor_sync(0xFFFFFFFFu, mi, off);
            if (om > m || (om == m && oi < mi)) { m = om; mi = oi; }
        }
        vals[r] = m; ids[r] = mi;
        if (mi == lane)            v0 = -1e30f;
        else if (mi == lane + 32)  v1 = -1e30f;
    }

    float s = 0.0f;
    #pragma unroll
    for (int r = 0; r < TOPK; r++) s += expf(vals[r] - vals[0]);

    if (lane < TOPK) {
        float myv = 0.0f; int myi = 0;
        #pragma unroll
        for (int r = 0; r < TOPK; r++)
            if (lane == r) { myv = vals[r]; myi = ids[r]; }
        float w = expf(myv - vals[0]) / s;
        g_topk_idx[t * TOPK + lane] = myi;
        g_topk_w[t * TOPK + lane]   = w;
        atomicAdd(&g_counts[myi], 1);
    }
}

// ---------------- exact fp32 64x64 GEMM (router only) -----------------------
__global__ void __launch_bounds__(256)
gemm64(const float* __restrict__ A, const float* __restrict__ B,
       float* __restrict__ C, int M, int Kd, int lda, int ldb, int ldc)
{
    __shared__ float As[16 * 65];
    __shared__ float Bs[16 * 64];
    const int tid = threadIdx.x;
    const int row0 = blockIdx.y * 64;
    const int col0 = blockIdx.x * 64;

    const int am = tid >> 2;
    const int ak = (tid & 3) << 2;
    const int bn = (tid & 15) << 2;
    const int bk = tid >> 4;
    const int ty = tid >> 4, tx = tid & 15;

    float acc[4][4];
    #pragma unroll
    for (int i = 0; i < 4; i++)
        #pragma unroll
        for (int j = 0; j < 4; j++) acc[i][j] = 0.0f;

    for (int k0 = 0; k0 < Kd; k0 += 16) {
        float4 av = *(const float4*)(A + (long)(row0 + am) * lda + k0 + ak);
        As[(ak + 0) * 65 + am] = av.x;
        As[(ak + 1) * 65 + am] = av.y;
        As[(ak + 2) * 65 + am] = av.z;
        As[(ak + 3) * 65 + am] = av.w;
        float4 bv = *(const float4*)(B + (long)(k0 + bk) * ldb + col0 + bn);
        *(float4*)&Bs[bk * 64 + bn] = bv;
        __syncthreads();
        #pragma unroll
        for (int k = 0; k < 16; k++) {
            float a0 = As[k * 65 + ty * 4 + 0];
            float a1 = As[k * 65 + ty * 4 + 1];
            float a2 = As[k * 65 + ty * 4 + 2];
            float a3 = As[k * 65 + ty * 4 + 3];
            float b0 = Bs[k * 64 + tx * 4 + 0];
            float b1 = Bs[k * 64 + tx * 4 + 1];
            float b2 = Bs[k * 64 + tx * 4 + 2];
            float b3 = Bs[k * 64 + tx * 4 + 3];
            acc[0][0] += a0 * b0; acc[0][1] += a0 * b1; acc[0][2] += a0 * b2; acc[0][3] += a0 * b3;
            acc[1][0] += a1 * b0; acc[1][1] += a1 * b1; acc[1][2] += a1 * b2; acc[1][3] += a1 * b3;
            acc[2][0] += a2 * b0; acc[2][1] += a2 * b1; acc[2][2] += a2 * b2; acc[2][3] += a2 * b3;
            acc[3][0] += a3 * b0; acc[3][1] += a3 * b1; acc[3][2] += a3 * b2; acc[3][3] += a3 * b3;
        }
        __syncthreads();
    }
    const int col = col0 + tx * 4;
    #pragma unroll
    for (int i = 0; i < 4; i++) {
        float* cp = C + (long)(row0 + ty * 4 + i) * ldc + col;
        #pragma unroll
        for (int j = 0; j < 4; j++) cp[j] = acc[i][j];
    }
}

// ---------------- fp16 tensor-core tile GEMM 128x128x32 ----------------------
// EXPERT: blockIdx.z selects expert window in g_offs + B stride
// GATHER: A row index = g_perm_tok[base + r]
// EPI: 0 = fp32 store, 1 = silu -> fp16 store, 2 = weighted fp32 atomicAdd at token row
template<bool EXPERT, bool GATHER, int EPI>
__global__ void __launch_bounds__(256, 2)
gemm_h(const __half* __restrict__ A, const __half* __restrict__ B,
       void* __restrict__ Cv, int Kd, int lda, int ldb, int ldc, long strideB)
{
    __shared__ char sm[SMEM_B];
    const int tid  = threadIdx.x;
    const int wid  = tid >> 5, lane = tid & 31;
    const int wM   = wid & 1,  wN   = wid >> 1;      // 2 x 4 warps, warp tile 64x32
    const int l16  = lane & 15, lh = lane >> 4;

    int base = 0, nrows = T_TOK;
    const __half* Bp = B;
    if (EXPERT) {
        int e = blockIdx.z;
        base  = g_offs[e];
        nrows = g_offs[e + 1] - base;
        Bp    = B + (long)e * strideB;
    }
    const int row0 = blockIdx.y * BM;
    if (EXPERT && row0 >= nrows) return;
    const int col0 = blockIdx.x * BN;

    const unsigned smu = (unsigned)__cvta_generic_to_shared(sm);
    const unsigned As_u = smu;              // stage0 A
    const unsigned Bs_u = smu + ASZ_B;      // stage0 B

    // cp.async bookkeeping: 2 A-chunks + 2 B-chunks per thread per stage
    const __half* asrc[2]; unsigned adst[2]; int abytes[2];
    #pragma unroll
    for (int i = 0; i < 2; i++) {
        int idx = tid + i * 256;
        int r = idx >> 2, q = idx & 3;              // 4 x 16B chunks per 32-fp16 row
        adst[i] = As_u + (unsigned)(r * ASTR_B + q * 16);
        int gr = row0 + r;
        long ar = -1;
        if (gr < nrows)
            ar = GATHER ? (long)g_perm_tok[base + gr]
                        : (EXPERT ? (long)(base + gr) : (long)gr);
        abytes[i] = (ar >= 0) ? 16 : 0;
        asrc[i] = A + (ar >= 0 ? ar : 0) * (long)lda + q * 8;
    }
    const __half* bsrc[2]; unsigned bdst[2];
    #pragma unroll
    for (int i = 0; i < 2; i++) {
        int idx = tid + i * 256;
        int br = idx >> 4, q = idx & 15;            // 16 x 16B chunks per 128-fp16 row
        bdst[i] = Bs_u + (unsigned)(br * BSTR_B + q * 16);
        bsrc[i] = Bp + (long)br * ldb + col0 + q * 8;
    }

    float acc[4][4][4];
    #pragma unroll
    for (int mi = 0; mi < 4; mi++)
        #pragma unroll
        for (int ni = 0; ni < 4; ni++)
            #pragma unroll
            for (int j = 0; j < 4; j++) acc[mi][ni][j] = 0.0f;

    const int nk = Kd / BK;

    // prefetch stage 0
    #pragma unroll
    for (int i = 0; i < 2; i++) cp16(adst[i], asrc[i], abytes[i]);
    #pragma unroll
    for (int i = 0; i < 2; i++) cp16(bdst[i], bsrc[i], 16);
    cp_commit();

    // ldmatrix base addresses (stage-relative)
    const unsigned a_base = As_u + (unsigned)((wM * 64 + l16) * ASTR_B + lh * 16);
    const unsigned b_base = Bs_u + (unsigned)(l16 * BSTR_B + (wN * 32) * 2 + lh * 16);

    for (int it = 0; it < nk; it++) {
        const int cur = it & 1;
        if (it + 1 < nk) {
            const int k0 = (it + 1) * BK;
            const unsigned soff = (cur == 0) ? (unsigned)STAGE_B : 0u;
            #pragma unroll
            for (int i = 0; i < 2; i++) cp16(adst[i] + soff, asrc[i] + k0, abytes[i]);
            #pragma unroll
            for (int i = 0; i < 2; i++) cp16(bdst[i] + soff, bsrc[i] + (long)k0 * ldb, 16);
            cp_commit();
            asm volatile("cp.async.wait_group 1;\n" ::);
        } else {
            asm volatile("cp.async.wait_group 0;\n" ::);
        }
        __syncthreads();

        const unsigned stoff = cur ? (unsigned)STAGE_B : 0u;
        #pragma unroll
        for (int ks = 0; ks < 2; ks++) {
            unsigned a[4][4], b[4][2];
            #pragma unroll
            for (int mi = 0; mi < 4; mi++)
                ldsm4(a[mi][0], a[mi][1], a[mi][2], a[mi][3],
                      a_base + stoff + (unsigned)(mi * 16 * ASTR_B + ks * 32));
            #pragma unroll
            for (int nb = 0; nb < 2; nb++)
                ldsm4t(b[nb * 2][0], b[nb * 2][1], b[nb * 2 + 1][0], b[nb * 2 + 1][1],
                       b_base + stoff + (unsigned)(ks * 16 * BSTR_B + nb * 32));
            #pragma unroll
            for (int mi = 0; mi < 4; mi++)
                #pragma unroll
                for (int ni = 0; ni < 4; ni++)
                    mma16816(acc[mi][ni], a[mi], b[ni]);
        }
        __syncthreads();
    }

    // epilogue
    const int lq = lane >> 2, lr2 = (lane & 3) * 2;
    #pragma unroll
    for (int mi = 0; mi < 4; mi++) {
        #pragma unroll
        for (int s = 0; s < 2; s++) {
            const int grow = row0 + wM * 64 + mi * 16 + lq + s * 8;
            if (grow >= nrows) continue;
            if (EPI == 2) {
                const int   tok = g_perm_tok[base + grow];
                const float w   = g_perm_w[base + grow];
                float* cp = (float*)Cv + (long)tok * ldc;
                #pragma unroll
                for (int ni = 0; ni < 4; ni++) {
                    const int col = col0 + wN * 32 + ni * 8 + lr2;
                    atomicAdd(&cp[col],     w * acc[mi][ni][2 * s]);
                    atomicAdd(&cp[col + 1], w * acc[mi][ni][2 * s + 1]);
                }
            } else if (EPI == 1) {
                const long cr = EXPERT ? (long)(base + grow) : (long)grow;
                __half* cp = (__half*)Cv + cr * ldc;
                #pragma unroll
                for (int ni = 0; ni < 4; ni++) {
                    const int col = col0 + wN * 32 + ni * 8 + lr2;
                    *(__half2*)&cp[col] = __floats2half2_rn(
                        silu_f(acc[mi][ni][2 * s]), silu_f(acc[mi][ni][2 * s + 1]));
                }
            } else {
                float* cp = (float*)Cv + (long)grow * ldc;
                #pragma unroll
                for (int ni = 0; ni < 4; ni++) {
                    const int col = col0 + wN * 32 + ni * 8 + lr2;
                    *(float2*)&cp[col] = make_float2(acc[mi][ni][2 * s], acc[mi][ni][2 * s + 1]);
                }
            }
        }
    }
}

// ---------------- launch (multi-stream fork/join under graph capture) --------
extern "C" void kernel_launch(void* const* d_in, const int* in_sizes, int n_in,
                              void* d_out, int out_size)
{
    const float* x   = (const float*)d_in[0];   // [T, H]
    const float* Ws1 = (const float*)d_in[1];   // [H, FF]
    const float* Ws2 = (const float*)d_in[2];   // [FF, H]
    const float* Wg  = (const float*)d_in[3];   // [H, E]
    const float* W1  = (const float*)d_in[4];   // [E, H, M]
    const float* W2  = (const float*)d_in[5];   // [E, M, H]

    float* out    = (float*)d_out;                      // [T, H]
    float* logits = out + (size_t)T_TOK * HDIM;         // [T, E]

    __half *xh, *s1h, *s2h, *w1h, *w2h, *h1h, *acth;
    cudaGetSymbolAddress((void**)&xh,  g_xh);
    cudaGetSymbolAddress((void**)&s1h, g_s1h);
    cudaGetSymbolAddress((void**)&s2h, g_s2h);
    cudaGetSymbolAddress((void**)&w1h, g_w1h);
    cudaGetSymbolAddress((void**)&w2h, g_w2h);
    cudaGetSymbolAddress((void**)&h1h, g_h1h);
    cudaGetSymbolAddress((void**)&acth, g_acth);

    cudaStream_t sConv, sRoute;
    cudaStreamCreateWithFlags(&sConv,  cudaStreamNonBlocking);
    cudaStreamCreateWithFlags(&sRoute, cudaStreamNonBlocking);
    cudaEvent_t e0, eWs1, eWs2, eW1, eW2, eRoute;
    cudaEventCreateWithFlags(&e0,     cudaEventDisableTiming);
    cudaEventCreateWithFlags(&eWs1,   cudaEventDisableTiming);
    cudaEventCreateWithFlags(&eWs2,   cudaEventDisableTiming);
    cudaEventCreateWithFlags(&eW1,    cudaEventDisableTiming);
    cudaEventCreateWithFlags(&eW2,    cudaEventDisableTiming);
    cudaEventCreateWithFlags(&eRoute, cudaEventDisableTiming);

    // fork from capture stream
    cudaEventRecord(e0, 0);
    cudaStreamWaitEvent(sConv,  e0, 0);
    cudaStreamWaitEvent(sRoute, e0, 0);

    // -- conversion branch (ordered by first use) --
    f2h_kernel<<<512, 256, 0, sConv>>>((const float4*)Ws1, (uint4*)s1h, (long)HDIM * FFDIM / 8);
    cudaEventRecord(eWs1, sConv);
    f2h_kernel<<<512, 256, 0, sConv>>>((const float4*)Ws2, (uint4*)s2h, (long)FFDIM * HDIM / 8);
    cudaEventRecord(eWs2, sConv);
    f2h_kernel<<<512, 256, 0, sConv>>>((const float4*)W1, (uint4*)w1h, (long)NEXP * HDIM * MDIM / 8);
    cudaEventRecord(eW1, sConv);
    f2h_kernel<<<512, 256, 0, sConv>>>((const float4*)W2, (uint4*)w2h, (long)NEXP * MDIM * HDIM / 8);
    cudaEventRecord(eW2, sConv);

    // -- router branch --
    zero_small_kernel<<<1, 128, 0, sRoute>>>();
    gemm64<<<dim3(1, T_TOK / 64, 1), 256, 0, sRoute>>>(x, Wg, logits, T_TOK, HDIM, HDIM, NEXP, NEXP);
    topk_kernel<<<T_TOK / 8, 256, 0, sRoute>>>(logits);
    scan_kernel<<<1, 32, 0, sRoute>>>();
    scatter_kernel<<<(NASSIGN + 255) / 256, 256, 0, sRoute>>>();
    cudaEventRecord(eRoute, sRoute);

    // -- main (capture) stream: x conversion, then the GEMM chain --
    f2h_kernel<<<512, 256>>>((const float4*)x, (uint4*)xh, (long)T_TOK * HDIM / 8);

    cudaStreamWaitEvent(0, eWs1, 0);
    gemm_h<false, false, 1><<<dim3(FFDIM / BN, T_TOK / BM, 1), 256>>>(
        xh, s1h, h1h, HDIM, HDIM, FFDIM, FFDIM, 0);

    cudaStreamWaitEvent(0, eWs2, 0);
    gemm_h<false, false, 0><<<dim3(HDIM / BN, T_TOK / BM, 1), 256>>>(
        h1h, s2h, out, FFDIM, FFDIM, HDIM, HDIM, 0);

    cudaStreamWaitEvent(0, eW1, 0);
    cudaStreamWaitEvent(0, eRoute, 0);
    gemm_h<true, true, 1><<<dim3(MDIM / BN, T_TOK / BM, NEXP), 256>>>(
        xh, w1h, acth, HDIM, HDIM, MDIM, MDIM, (long)HDIM * MDIM);

    cudaStreamWaitEvent(0, eW2, 0);
    gemm_h<true, false, 2><<<dim3(HDIM / BN, T_TOK / BM, NEXP), 256>>>(
        acth, w2h, out, MDIM, MDIM, HDIM, HDIM, (long)MDIM * HDIM);

    // join complete (all forked streams rejoined via event waits above)
    cudaEventDestroy(e0);
    cudaEventDestroy(eWs1);
    cudaEventDestroy(eWs2);
    cudaEventDestroy(eW1);
    cudaEventDestroy(eW2);
    cudaEventDestroy(eRoute);
    cudaStreamDestroy(sConv);
    cudaStreamDestroy(sRoute);
}